// round 3
// baseline (speedup 1.0000x reference)
#include <cuda_runtime.h>
#include <math.h>

// ---------------- problem constants ----------------
#define U_N 100000
#define I_N 150000
#define DD  64
#define NNZ_UI 2000000
#define NNZ_S  1000000
#define B_N 4096
#define LN_EPS 1e-5f

// ---------------- scratch (device globals; no allocation allowed) ----------------
__device__ __align__(128) float g_u1[(size_t)U_N * DD];   // LightGCN user layer 1 (incl 0.1*E0)
__device__ __align__(128) float g_u2[(size_t)U_N * DD];   // LightGCN user layer 2
__device__ __align__(128) float g_s1[(size_t)U_N * DD];   // social layer 1 output
__device__ __align__(128) float g_y [(size_t)U_N * DD];   // cur @ Wsoc[l] (reused both layers)
__device__ __align__(128) float g_n [(size_t)U_N * DD];   // new = cur + neighbor (reused both layers)
__device__ __align__(128) float g_i1[(size_t)I_N * DD];   // item layer 1
__device__ __align__(128) float g_i2[(size_t)I_N * DD];   // item layer 2 (only batch rows valid)
__device__ int   g_uflag[U_N];
__device__ int   g_iflag[I_N];
__device__ float g_nw[3];

// ---------------- helpers ----------------
__device__ __forceinline__ void red2(float* a, float x, float y) {
    atomicAdd(a, x);
    atomicAdd(a + 1, y);
}

__device__ __forceinline__ float warp_sum(float v) {
    #pragma unroll
    for (int o = 16; o > 0; o >>= 1) v += __shfl_xor_sync(0xffffffffu, v, o);
    return v;
}

// out[2*lane], out[2*lane+1] of (x[0..63] @ W[64x64]); x distributed as float2/lane.
__device__ __forceinline__ float2 row_gemm64(float2 xv, const float2* __restrict__ W2, int lane) {
    float2 acc = make_float2(0.f, 0.f);
    #pragma unroll
    for (int kk = 0; kk < 32; kk++) {
        float x0 = __shfl_sync(0xffffffffu, xv.x, kk);
        float x1 = __shfl_sync(0xffffffffu, xv.y, kk);
        float2 w0 = W2[(2 * kk) * 32 + lane];
        float2 w1 = W2[(2 * kk + 1) * 32 + lane];
        acc.x = fmaf(x0, w0.x, fmaf(x1, w1.x, acc.x));
        acc.y = fmaf(x0, w0.y, fmaf(x1, w1.y, acc.y));
    }
    return acc;
}

// ---------------- init kernels ----------------
__global__ void k_clear_flags() {
    for (int i = blockIdx.x * blockDim.x + threadIdx.x; i < I_N;
         i += gridDim.x * blockDim.x) {
        if (i < U_N) g_uflag[i] = 0;
        g_iflag[i] = 0;
    }
}

// mark batch rows + init i2 batch rows to 0.1*item_emb
__global__ void k_mark(const int* __restrict__ users, const int* __restrict__ pos,
                       const float* __restrict__ ie) {
    int t = blockIdx.x * blockDim.x + threadIdx.x;
    int wb = t >> 5, lane = t & 31;
    if (wb >= B_N) return;
    int u = users[wb], p = pos[wb];
    if (lane == 0) { g_uflag[u] = 1; g_iflag[p] = 1; }
    float2 v = ((const float2*)(ie + (size_t)p * DD))[lane];
    ((float2*)(g_i2 + (size_t)p * DD))[lane] = make_float2(0.1f * v.x, 0.1f * v.y);
}

__global__ void k_init_u(const float* __restrict__ ue) {
    int i = blockIdx.x * blockDim.x + threadIdx.x;
    if (i >= U_N * DD / 4) return;
    float4 v = ((const float4*)ue)[i];
    float4 w = make_float4(0.1f * v.x, 0.1f * v.y, 0.1f * v.z, 0.1f * v.w);
    ((float4*)g_u1)[i] = w;
    ((float4*)g_u2)[i] = w;
}

__global__ void k_init_i(const float* __restrict__ ie) {
    int i = blockIdx.x * blockDim.x + threadIdx.x;
    if (i >= I_N * DD / 4) return;
    float4 v = ((const float4*)ie)[i];
    ((float4*)g_i1)[i] = make_float4(0.1f * v.x, 0.1f * v.y, 0.1f * v.z, 0.1f * v.w);
}

// softmax over layer_weights[0:3]
__global__ void k_nw(const float* __restrict__ lw) {
    float a = lw[0], b = lw[1], c = lw[2];
    float m = fmaxf(a, fmaxf(b, c));
    float e0 = expf(a - m), e1 = expf(b - m), e2 = expf(c - m);
    float inv = 1.f / (e0 + e1 + e2);
    g_nw[0] = e0 * inv; g_nw[1] = e1 * inv; g_nw[2] = e2 * inv;
}

// ---------------- spmm kernels (warp per edge) ----------------
// pass 1: u1[src] += w * item_emb[dst];  i1[dst] += w * user_emb[src]
__global__ void k_spmm_pass1(const int* __restrict__ src, const int* __restrict__ dst,
                             const float* __restrict__ w,
                             const float* __restrict__ ue, const float* __restrict__ ie) {
    int t = blockIdx.x * blockDim.x + threadIdx.x;
    int e = t >> 5, lane = t & 31;
    if (e >= NNZ_UI) return;
    int s = src[e], d = dst[e];
    float we = w[e];
    float2 a = ((const float2*)(ie + (size_t)d * DD))[lane];
    float2 b = ((const float2*)(ue + (size_t)s * DD))[lane];
    red2(&g_u1[(size_t)s * DD + 2 * lane], we * a.x, we * a.y);
    red2(&g_i1[(size_t)d * DD + 2 * lane], we * b.x, we * b.y);
}

// pass 2: u2[src] += w * i1[dst];  (batch items only) i2[dst] += w * u1[src]
__global__ void k_spmm_pass2(const int* __restrict__ src, const int* __restrict__ dst,
                             const float* __restrict__ w) {
    int t = blockIdx.x * blockDim.x + threadIdx.x;
    int e = t >> 5, lane = t & 31;
    if (e >= NNZ_UI) return;
    int s = src[e], d = dst[e];
    float we = w[e];
    const float* __restrict__ i1 = g_i1;
    float2 a = ((const float2*)(i1 + (size_t)d * DD))[lane];
    red2(&g_u2[(size_t)s * DD + 2 * lane], we * a.x, we * a.y);
    int flag = (lane == 0) ? g_iflag[d] : 0;
    flag = __shfl_sync(0xffffffffu, flag, 0);
    if (flag) {
        const float* __restrict__ u1 = g_u1;
        float2 b = ((const float2*)(u1 + (size_t)s * DD))[lane];
        red2(&g_i2[(size_t)d * DD + 2 * lane], we * b.x, we * b.y);
    }
}

// social spmm: n[src] += w * y[dst]; filtered => only batch-user src rows
__global__ void k_spmm_soc(const int* __restrict__ src, const int* __restrict__ dst,
                           const float* __restrict__ w, int filtered) {
    int t = blockIdx.x * blockDim.x + threadIdx.x;
    int e = t >> 5, lane = t & 31;
    if (e >= NNZ_S) return;
    int s = src[e];
    if (filtered) {
        int flag = (lane == 0) ? g_uflag[s] : 0;
        if (!__shfl_sync(0xffffffffu, flag, 0)) return;
    }
    int d = dst[e];
    float we = w[e];
    const float* __restrict__ y = g_y;
    float2 a = ((const float2*)(y + (size_t)d * DD))[lane];
    red2(&g_n[(size_t)s * DD + 2 * lane], we * a.x, we * a.y);
}

// ---------------- dense kernels ----------------
// y = X @ Wsoc[l]; also n = X (so scatter lands on new = cur + neighbor). xmode: 0 -> u2, 1 -> s1
__global__ void k_gemm64(const float* __restrict__ Wg, int xmode, int nrows) {
    __shared__ float sW[64 * 64];
    for (int i = threadIdx.x; i < 1024; i += blockDim.x)
        ((float4*)sW)[i] = ((const float4*)Wg)[i];
    __syncthreads();
    const float* __restrict__ X = xmode ? g_s1 : g_u2;
    const float2* W2 = (const float2*)sW;
    int lane = threadIdx.x & 31;
    int gw = (blockIdx.x * blockDim.x + threadIdx.x) >> 5;
    int tw = (gridDim.x * blockDim.x) >> 5;
    for (int r = gw; r < nrows; r += tw) {
        float2 xv = ((const float2*)(X + (size_t)r * DD))[lane];
        ((float2*)(g_n + (size_t)r * DD))[lane] = xv;
        float2 acc = row_gemm64(xv, W2, lane);
        ((float2*)(g_y + (size_t)r * DD))[lane] = acc;
    }
}

// social layer-1 epilogue over ALL users:
// s1 = gate * new + (1-gate) * u2, gate = sigmoid(lrelu(LN(new @ hoW + hob)))
__global__ void k_social1(const float* __restrict__ hoW, const float* __restrict__ hob,
                          const float* __restrict__ hog, const float* __restrict__ hobeta) {
    __shared__ float sW[64 * 64];
    for (int i = threadIdx.x; i < 1024; i += blockDim.x)
        ((float4*)sW)[i] = ((const float4*)hoW)[i];
    __syncthreads();
    int lane = threadIdx.x & 31;
    int j0 = 2 * lane, j1 = 2 * lane + 1;
    int gw = (blockIdx.x * blockDim.x + threadIdx.x) >> 5;
    int tw = (gridDim.x * blockDim.x) >> 5;
    float b0 = hob[j0], b1 = hob[j1];
    float gg0 = hog[j0], gg1 = hog[j1];
    float be0 = hobeta[j0], be1 = hobeta[j1];
    for (int r = gw; r < U_N; r += tw) {
        float2 nv = ((const float2*)(g_n + (size_t)r * DD))[lane];
        float2 hv = row_gemm64(nv, (const float2*)sW, lane);
        hv.x += b0; hv.y += b1;
        float mu  = warp_sum(hv.x + hv.y) * (1.f / 64.f);
        float msq = warp_sum(hv.x * hv.x + hv.y * hv.y) * (1.f / 64.f);
        float inv = rsqrtf(msq - mu * mu + LN_EPS);
        float t0 = (hv.x - mu) * inv * gg0 + be0;
        float t1 = (hv.y - mu) * inv * gg1 + be1;
        t0 = t0 >= 0.f ? t0 : 0.01f * t0;
        t1 = t1 >= 0.f ? t1 : 0.01f * t1;
        float ga = 1.f / (1.f + expf(-t0));
        float gb = 1.f / (1.f + expf(-t1));
        float2 cv = ((const float2*)(g_u2 + (size_t)r * DD))[lane];
        float2 o;
        o.x = ga * nv.x + (1.f - ga) * cv.x;
        o.y = gb * nv.y + (1.f - gb) * cv.y;
        ((float2*)(g_s1 + (size_t)r * DD))[lane] = o;
    }
}

// final: per batch row — social layer-2 epilogue + aggregates + metapath fusion + score
__global__ void k_final(const int* __restrict__ users, const int* __restrict__ pos,
                        const float* __restrict__ ue, const float* __restrict__ ie,
                        const float* __restrict__ hoW, const float* __restrict__ hob,
                        const float* __restrict__ hog, const float* __restrict__ hobeta,
                        const float* __restrict__ mpW, const float* __restrict__ mpb,
                        const float* __restrict__ mpg, const float* __restrict__ mpbeta,
                        float* __restrict__ out) {
    int t = blockIdx.x * blockDim.x + threadIdx.x;
    int wb = t >> 5, lane = t & 31;
    if (wb >= B_N) return;
    int u = users[wb], p = pos[wb];
    int j0 = 2 * lane, j1 = 2 * lane + 1;
    float nw0 = g_nw[0], nw1 = g_nw[1], nw2 = g_nw[2];

    // ---- social layer 2 epilogue (new2 lives in g_n, cur = s1)
    float2 nv = ((const float2*)(g_n + (size_t)u * DD))[lane];
    float2 hv = row_gemm64(nv, (const float2*)hoW, lane);
    hv.x += hob[j0]; hv.y += hob[j1];
    float mu  = warp_sum(hv.x + hv.y) * (1.f / 64.f);
    float msq = warp_sum(hv.x * hv.x + hv.y * hv.y) * (1.f / 64.f);
    float inv = rsqrtf(msq - mu * mu + LN_EPS);
    float t0 = (hv.x - mu) * inv * hog[j0] + hobeta[j0];
    float t1 = (hv.y - mu) * inv * hog[j1] + hobeta[j1];
    t0 = t0 >= 0.f ? t0 : 0.01f * t0;
    t1 = t1 >= 0.f ? t1 : 0.01f * t1;
    float ga = 1.f / (1.f + expf(-t0));
    float gb = 1.f / (1.f + expf(-t1));
    float2 cv = ((const float2*)(g_s1 + (size_t)u * DD))[lane];
    float2 s2;
    s2.x = ga * nv.x + (1.f - ga) * cv.x;
    s2.y = gb * nv.y + (1.f - gb) * cv.y;

    // ---- aggregates (softmax-weighted sums over 3 layers)
    float2 u2v = ((const float2*)(g_u2 + (size_t)u * DD))[lane];
    float2 swv;  // social_weighted, s_list = [u2, s1, s2]
    swv.x = nw0 * u2v.x + nw1 * cv.x + nw2 * s2.x;
    swv.y = nw0 * u2v.y + nw1 * cv.y + nw2 * s2.y;
    float2 e0 = ((const float2*)(ue + (size_t)u * DD))[lane];
    float2 u1v = ((const float2*)(g_u1 + (size_t)u * DD))[lane];
    float2 uwv;  // user_weighted, u_list = [E0, u1, u2]
    uwv.x = nw0 * e0.x + nw1 * u1v.x + nw2 * u2v.x;
    uwv.y = nw0 * e0.y + nw1 * u1v.y + nw2 * u2v.y;

    // ---- metapath fusion: concat(uw, sw) @ mpW[128x64] + mpb -> LN -> leaky
    float2 acc = row_gemm64(uwv, (const float2*)mpW, lane);
    float2 acc2 = row_gemm64(swv, (const float2*)mpW + 64 * 32, lane);
    acc.x += acc2.x + mpb[j0];
    acc.y += acc2.y + mpb[j1];
    float mu2  = warp_sum(acc.x + acc.y) * (1.f / 64.f);
    float msq2 = warp_sum(acc.x * acc.x + acc.y * acc.y) * (1.f / 64.f);
    float inv2 = rsqrtf(msq2 - mu2 * mu2 + LN_EPS);
    float f0 = (acc.x - mu2) * inv2 * mpg[j0] + mpbeta[j0];
    float f1 = (acc.y - mu2) * inv2 * mpg[j1] + mpbeta[j1];
    f0 = f0 >= 0.f ? f0 : 0.01f * f0;
    f1 = f1 >= 0.f ? f1 : 0.01f * f1;

    // ---- item_weighted at pos item, then dot
    float2 ei  = ((const float2*)(ie + (size_t)p * DD))[lane];
    float2 i1v = ((const float2*)(g_i1 + (size_t)p * DD))[lane];
    float2 i2v = ((const float2*)(g_i2 + (size_t)p * DD))[lane];
    float iw0 = nw0 * ei.x + nw1 * i1v.x + nw2 * i2v.x;
    float iw1 = nw0 * ei.y + nw1 * i1v.y + nw2 * i2v.y;
    float sc = warp_sum(f0 * iw0 + f1 * iw1);
    if (lane == 0) out[wb] = sc;
}

// ---------------- launch ----------------
extern "C" void kernel_launch(void* const* d_in, const int* in_sizes, int n_in,
                              void* d_out, int out_size) {
    (void)in_sizes; (void)n_in; (void)out_size;
    const int*   users  = (const int*)d_in[0];
    const int*   pos    = (const int*)d_in[1];
    const int*   ui_src = (const int*)d_in[2];
    const int*   ui_dst = (const int*)d_in[3];
    const float* ui_w   = (const float*)d_in[4];
    const int*   s_src  = (const int*)d_in[5];
    const int*   s_dst  = (const int*)d_in[6];
    const float* s_w    = (const float*)d_in[7];
    const float* ue     = (const float*)d_in[8];
    const float* ie     = (const float*)d_in[9];
    const float* lw     = (const float*)d_in[10];
    const float* Wsoc   = (const float*)d_in[11];
    const float* hoW    = (const float*)d_in[12];
    const float* hob    = (const float*)d_in[13];
    const float* hog    = (const float*)d_in[14];
    const float* hobeta = (const float*)d_in[15];
    const float* mpW    = (const float*)d_in[16];
    const float* mpb    = (const float*)d_in[17];
    const float* mpg    = (const float*)d_in[18];
    const float* mpbeta = (const float*)d_in[19];
    float* out = (float*)d_out;

    k_clear_flags<<<(I_N + 255) / 256, 256>>>();
    k_mark<<<B_N / 8, 256>>>(users, pos, ie);
    k_init_u<<<(U_N * DD / 4 + 255) / 256, 256>>>(ue);
    k_init_i<<<(I_N * DD / 4 + 255) / 256, 256>>>(ie);
    k_nw<<<1, 1>>>(lw);

    // LightGCN layer 1 (fused u1 & i1), then layer 2 (u2 full, i2 batch-filtered)
    k_spmm_pass1<<<NNZ_UI / 8, 256>>>(ui_src, ui_dst, ui_w, ue, ie);
    k_spmm_pass2<<<NNZ_UI / 8, 256>>>(ui_src, ui_dst, ui_w);

    // Social layer 1 (full graph)
    k_gemm64<<<592, 256>>>(Wsoc, /*xmode=*/0, U_N);           // y = u2 @ Wsoc[0]; n = u2
    k_spmm_soc<<<NNZ_S / 8, 256>>>(s_src, s_dst, s_w, 0);     // n = new1
    k_social1<<<592, 256>>>(hoW, hob, hog, hobeta);           // s1

    // Social layer 2 (output needed only at batch users)
    k_gemm64<<<592, 256>>>(Wsoc + DD * DD, /*xmode=*/1, U_N); // y = s1 @ Wsoc[1]; n = s1
    k_spmm_soc<<<NNZ_S / 8, 256>>>(s_src, s_dst, s_w, 1);     // n = new2 (batch rows)

    // Epilogue + fusion + scoring, batch rows only
    k_final<<<B_N / 8, 256>>>(users, pos, ue, ie, hoW, hob, hog, hobeta,
                              mpW, mpb, mpg, mpbeta, out);
}

// round 4
// speedup vs baseline: 1.4757x; 1.4757x over previous
#include <cuda_runtime.h>
#include <math.h>

// ---------------- problem constants ----------------
#define U_N 100000
#define I_N 150000
#define DD  64
#define NNZ_UI 2000000
#define NNZ_S  1000000
#define B_N 4096
#define LN_EPS 1e-5f

// ---------------- scratch (device globals; no allocation allowed) ----------------
__device__ __align__(128) float g_u1[(size_t)U_N * DD];   // LightGCN user layer 1 (incl 0.1*E0)
__device__ __align__(128) float g_u2[(size_t)U_N * DD];   // LightGCN user layer 2
__device__ __align__(128) float g_s1[(size_t)U_N * DD];   // social layer 1 output
__device__ __align__(128) float g_y [(size_t)U_N * DD];   // cur @ Wsoc[l] (reused both layers)
__device__ __align__(128) float g_n [(size_t)U_N * DD];   // new = cur + neighbor (reused both layers)
__device__ __align__(128) float g_i1[(size_t)I_N * DD];   // item layer 1
__device__ __align__(128) float g_i2[(size_t)I_N * DD];   // item layer 2 (only batch rows valid)
__device__ int   g_uflag[U_N];
__device__ int   g_iflag[I_N];
__device__ float g_nw[3];

// ---------------- helpers ----------------
__device__ __forceinline__ float warp_sum(float v) {
    #pragma unroll
    for (int o = 16; o > 0; o >>= 1) v += __shfl_xor_sync(0xffffffffu, v, o);
    return v;
}

// out[2*lane], out[2*lane+1] of (x[0..63] @ W[64x64]); x distributed as float2/lane.
__device__ __forceinline__ float2 row_gemm64(float2 xv, const float2* __restrict__ W2, int lane) {
    float2 acc = make_float2(0.f, 0.f);
    #pragma unroll
    for (int kk = 0; kk < 32; kk++) {
        float x0 = __shfl_sync(0xffffffffu, xv.x, kk);
        float x1 = __shfl_sync(0xffffffffu, xv.y, kk);
        float2 w0 = W2[(2 * kk) * 32 + lane];
        float2 w1 = W2[(2 * kk + 1) * 32 + lane];
        acc.x = fmaf(x0, w0.x, fmaf(x1, w1.x, acc.x));
        acc.y = fmaf(x0, w0.y, fmaf(x1, w1.y, acc.y));
    }
    return acc;
}

// ---------------- init kernels ----------------
__global__ void k_clear_flags() {
    for (int i = blockIdx.x * blockDim.x + threadIdx.x; i < I_N;
         i += gridDim.x * blockDim.x) {
        if (i < U_N) g_uflag[i] = 0;
        g_iflag[i] = 0;
    }
}

// mark batch rows + init i2 batch rows to 0.1*item_emb
__global__ void k_mark(const int* __restrict__ users, const int* __restrict__ pos,
                       const float* __restrict__ ie) {
    int t = blockIdx.x * blockDim.x + threadIdx.x;
    int wb = t >> 5, lane = t & 31;
    if (wb >= B_N) return;
    int u = users[wb], p = pos[wb];
    if (lane == 0) { g_uflag[u] = 1; g_iflag[p] = 1; }
    float2 v = ((const float2*)(ie + (size_t)p * DD))[lane];
    ((float2*)(g_i2 + (size_t)p * DD))[lane] = make_float2(0.1f * v.x, 0.1f * v.y);
}

__global__ void k_init_u(const float* __restrict__ ue) {
    int i = blockIdx.x * blockDim.x + threadIdx.x;
    if (i >= U_N * DD / 4) return;
    float4 v = ((const float4*)ue)[i];
    float4 w = make_float4(0.1f * v.x, 0.1f * v.y, 0.1f * v.z, 0.1f * v.w);
    ((float4*)g_u1)[i] = w;
    ((float4*)g_u2)[i] = w;
}

__global__ void k_init_i(const float* __restrict__ ie) {
    int i = blockIdx.x * blockDim.x + threadIdx.x;
    if (i >= I_N * DD / 4) return;
    float4 v = ((const float4*)ie)[i];
    ((float4*)g_i1)[i] = make_float4(0.1f * v.x, 0.1f * v.y, 0.1f * v.z, 0.1f * v.w);
}

// softmax over layer_weights[0:3]
__global__ void k_nw(const float* __restrict__ lw) {
    float a = lw[0], b = lw[1], c = lw[2];
    float m = fmaxf(a, fmaxf(b, c));
    float e0 = expf(a - m), e1 = expf(b - m), e2 = expf(c - m);
    float inv = 1.f / (e0 + e1 + e2);
    g_nw[0] = e0 * inv; g_nw[1] = e1 * inv; g_nw[2] = e2 * inv;
}

// ---------------- spmm kernels (16 threads per edge, float4 atomics) ----------------
// pass 1: u1[src] += w * item_emb[dst];  i1[dst] += w * user_emb[src]
__global__ void k_spmm_pass1(const int* __restrict__ src, const int* __restrict__ dst,
                             const float* __restrict__ w,
                             const float* __restrict__ ue, const float* __restrict__ ie) {
    int t = blockIdx.x * blockDim.x + threadIdx.x;
    int e = t >> 4, q = t & 15;
    if (e >= NNZ_UI) return;
    int s = src[e], d = dst[e];
    float we = w[e];
    float4 a = ((const float4*)(ie + (size_t)d * DD))[q];
    float4 b = ((const float4*)(ue + (size_t)s * DD))[q];
    atomicAdd(((float4*)(g_u1 + (size_t)s * DD)) + q,
              make_float4(we * a.x, we * a.y, we * a.z, we * a.w));
    atomicAdd(((float4*)(g_i1 + (size_t)d * DD)) + q,
              make_float4(we * b.x, we * b.y, we * b.z, we * b.w));
}

// pass 2: u2[src] += w * i1[dst];  (batch items only) i2[dst] += w * u1[src]
__global__ void k_spmm_pass2(const int* __restrict__ src, const int* __restrict__ dst,
                             const float* __restrict__ w) {
    int t = blockIdx.x * blockDim.x + threadIdx.x;
    int e = t >> 4, q = t & 15;
    if (e >= NNZ_UI) return;
    int s = src[e], d = dst[e];
    float we = w[e];
    const float* __restrict__ i1 = g_i1;
    float4 a = ((const float4*)(i1 + (size_t)d * DD))[q];
    atomicAdd(((float4*)(g_u2 + (size_t)s * DD)) + q,
              make_float4(we * a.x, we * a.y, we * a.z, we * a.w));
    if (g_iflag[d]) {   // uniform across the 16-thread group (same d)
        const float* __restrict__ u1 = g_u1;
        float4 b = ((const float4*)(u1 + (size_t)s * DD))[q];
        atomicAdd(((float4*)(g_i2 + (size_t)d * DD)) + q,
                  make_float4(we * b.x, we * b.y, we * b.z, we * b.w));
    }
}

// social spmm: n[src] += w * y[dst]; filtered => only batch-user src rows
__global__ void k_spmm_soc(const int* __restrict__ src, const int* __restrict__ dst,
                           const float* __restrict__ w, int filtered) {
    int t = blockIdx.x * blockDim.x + threadIdx.x;
    int e = t >> 4, q = t & 15;
    if (e >= NNZ_S) return;
    int s = src[e];
    if (filtered && !g_uflag[s]) return;
    int d = dst[e];
    float we = w[e];
    const float* __restrict__ y = g_y;
    float4 a = ((const float4*)(y + (size_t)d * DD))[q];
    atomicAdd(((float4*)(g_n + (size_t)s * DD)) + q,
              make_float4(we * a.x, we * a.y, we * a.z, we * a.w));
}

// ---------------- dense kernels ----------------
// y = u2 @ Wsoc[0]; n = u2 (scatter destination pre-init)
__global__ void k_gemm64(const float* __restrict__ Wg) {
    __shared__ float sW[64 * 64];
    for (int i = threadIdx.x; i < 1024; i += blockDim.x)
        ((float4*)sW)[i] = ((const float4*)Wg)[i];
    __syncthreads();
    const float* __restrict__ X = g_u2;
    const float2* W2 = (const float2*)sW;
    int lane = threadIdx.x & 31;
    int gw = (blockIdx.x * blockDim.x + threadIdx.x) >> 5;
    int tw = (gridDim.x * blockDim.x) >> 5;
    for (int r = gw; r < U_N; r += tw) {
        float2 xv = ((const float2*)(X + (size_t)r * DD))[lane];
        ((float2*)(g_n + (size_t)r * DD))[lane] = xv;
        float2 acc = row_gemm64(xv, W2, lane);
        ((float2*)(g_y + (size_t)r * DD))[lane] = acc;
    }
}

// social layer-1 epilogue over ALL users, fused with layer-2 input GEMM:
//   s1 = gate*new + (1-gate)*u2, gate = sigmoid(lrelu(LN(new @ hoW + hob)))
//   then y = s1 @ Wsoc[1], n = s1 (pre-init for the layer-2 scatter)
__global__ void k_social1(const float* __restrict__ hoW, const float* __restrict__ hob,
                          const float* __restrict__ hog, const float* __restrict__ hobeta,
                          const float* __restrict__ Wsoc1) {
    __shared__ float sW[64 * 64];
    __shared__ float sV[64 * 64];
    for (int i = threadIdx.x; i < 1024; i += blockDim.x) {
        ((float4*)sW)[i] = ((const float4*)hoW)[i];
        ((float4*)sV)[i] = ((const float4*)Wsoc1)[i];
    }
    __syncthreads();
    int lane = threadIdx.x & 31;
    int j0 = 2 * lane, j1 = 2 * lane + 1;
    int gw = (blockIdx.x * blockDim.x + threadIdx.x) >> 5;
    int tw = (gridDim.x * blockDim.x) >> 5;
    float b0 = hob[j0], b1 = hob[j1];
    float gg0 = hog[j0], gg1 = hog[j1];
    float be0 = hobeta[j0], be1 = hobeta[j1];
    for (int r = gw; r < U_N; r += tw) {
        float2 nv = ((const float2*)(g_n + (size_t)r * DD))[lane];
        float2 hv = row_gemm64(nv, (const float2*)sW, lane);
        hv.x += b0; hv.y += b1;
        float mu  = warp_sum(hv.x + hv.y) * (1.f / 64.f);
        float msq = warp_sum(hv.x * hv.x + hv.y * hv.y) * (1.f / 64.f);
        float inv = rsqrtf(msq - mu * mu + LN_EPS);
        float t0 = (hv.x - mu) * inv * gg0 + be0;
        float t1 = (hv.y - mu) * inv * gg1 + be1;
        t0 = t0 >= 0.f ? t0 : 0.01f * t0;
        t1 = t1 >= 0.f ? t1 : 0.01f * t1;
        float ga = 1.f / (1.f + expf(-t0));
        float gb = 1.f / (1.f + expf(-t1));
        float2 cv = ((const float2*)(g_u2 + (size_t)r * DD))[lane];
        float2 o;
        o.x = ga * nv.x + (1.f - ga) * cv.x;
        o.y = gb * nv.y + (1.f - gb) * cv.y;
        ((float2*)(g_s1 + (size_t)r * DD))[lane] = o;
        ((float2*)(g_n  + (size_t)r * DD))[lane] = o;
        float2 y2 = row_gemm64(o, (const float2*)sV, lane);
        ((float2*)(g_y + (size_t)r * DD))[lane] = y2;
    }
}

// final: per batch row — social layer-2 epilogue + aggregates + metapath fusion + score
__global__ void k_final(const int* __restrict__ users, const int* __restrict__ pos,
                        const float* __restrict__ ue, const float* __restrict__ ie,
                        const float* __restrict__ hoW, const float* __restrict__ hob,
                        const float* __restrict__ hog, const float* __restrict__ hobeta,
                        const float* __restrict__ mpW, const float* __restrict__ mpb,
                        const float* __restrict__ mpg, const float* __restrict__ mpbeta,
                        float* __restrict__ out) {
    int t = blockIdx.x * blockDim.x + threadIdx.x;
    int wb = t >> 5, lane = t & 31;
    if (wb >= B_N) return;
    int u = users[wb], p = pos[wb];
    int j0 = 2 * lane, j1 = 2 * lane + 1;
    float nw0 = g_nw[0], nw1 = g_nw[1], nw2 = g_nw[2];

    // ---- social layer 2 epilogue (new2 lives in g_n, cur = s1)
    float2 nv = ((const float2*)(g_n + (size_t)u * DD))[lane];
    float2 hv = row_gemm64(nv, (const float2*)hoW, lane);
    hv.x += hob[j0]; hv.y += hob[j1];
    float mu  = warp_sum(hv.x + hv.y) * (1.f / 64.f);
    float msq = warp_sum(hv.x * hv.x + hv.y * hv.y) * (1.f / 64.f);
    float inv = rsqrtf(msq - mu * mu + LN_EPS);
    float t0 = (hv.x - mu) * inv * hog[j0] + hobeta[j0];
    float t1 = (hv.y - mu) * inv * hog[j1] + hobeta[j1];
    t0 = t0 >= 0.f ? t0 : 0.01f * t0;
    t1 = t1 >= 0.f ? t1 : 0.01f * t1;
    float ga = 1.f / (1.f + expf(-t0));
    float gb = 1.f / (1.f + expf(-t1));
    float2 cv = ((const float2*)(g_s1 + (size_t)u * DD))[lane];
    float2 s2;
    s2.x = ga * nv.x + (1.f - ga) * cv.x;
    s2.y = gb * nv.y + (1.f - gb) * cv.y;

    // ---- aggregates (softmax-weighted sums over 3 layers)
    float2 u2v = ((const float2*)(g_u2 + (size_t)u * DD))[lane];
    float2 swv;  // social_weighted, s_list = [u2, s1, s2]
    swv.x = nw0 * u2v.x + nw1 * cv.x + nw2 * s2.x;
    swv.y = nw0 * u2v.y + nw1 * cv.y + nw2 * s2.y;
    float2 e0 = ((const float2*)(ue + (size_t)u * DD))[lane];
    float2 u1v = ((const float2*)(g_u1 + (size_t)u * DD))[lane];
    float2 uwv;  // user_weighted, u_list = [E0, u1, u2]
    uwv.x = nw0 * e0.x + nw1 * u1v.x + nw2 * u2v.x;
    uwv.y = nw0 * e0.y + nw1 * u1v.y + nw2 * u2v.y;

    // ---- metapath fusion: concat(uw, sw) @ mpW[128x64] + mpb -> LN -> leaky
    float2 acc = row_gemm64(uwv, (const float2*)mpW, lane);
    float2 acc2 = row_gemm64(swv, (const float2*)mpW + 64 * 32, lane);
    acc.x += acc2.x + mpb[j0];
    acc.y += acc2.y + mpb[j1];
    float mu2  = warp_sum(acc.x + acc.y) * (1.f / 64.f);
    float msq2 = warp_sum(acc.x * acc.x + acc.y * acc.y) * (1.f / 64.f);
    float inv2 = rsqrtf(msq2 - mu2 * mu2 + LN_EPS);
    float f0 = (acc.x - mu2) * inv2 * mpg[j0] + mpbeta[j0];
    float f1 = (acc.y - mu2) * inv2 * mpg[j1] + mpbeta[j1];
    f0 = f0 >= 0.f ? f0 : 0.01f * f0;
    f1 = f1 >= 0.f ? f1 : 0.01f * f1;

    // ---- item_weighted at pos item, then dot
    float2 ei  = ((const float2*)(ie + (size_t)p * DD))[lane];
    float2 i1v = ((const float2*)(g_i1 + (size_t)p * DD))[lane];
    float2 i2v = ((const float2*)(g_i2 + (size_t)p * DD))[lane];
    float iw0 = nw0 * ei.x + nw1 * i1v.x + nw2 * i2v.x;
    float iw1 = nw0 * ei.y + nw1 * i1v.y + nw2 * i2v.y;
    float sc = warp_sum(f0 * iw0 + f1 * iw1);
    if (lane == 0) out[wb] = sc;
}

// ---------------- launch ----------------
extern "C" void kernel_launch(void* const* d_in, const int* in_sizes, int n_in,
                              void* d_out, int out_size) {
    (void)in_sizes; (void)n_in; (void)out_size;
    const int*   users  = (const int*)d_in[0];
    const int*   pos    = (const int*)d_in[1];
    const int*   ui_src = (const int*)d_in[2];
    const int*   ui_dst = (const int*)d_in[3];
    const float* ui_w   = (const float*)d_in[4];
    const int*   s_src  = (const int*)d_in[5];
    const int*   s_dst  = (const int*)d_in[6];
    const float* s_w    = (const float*)d_in[7];
    const float* ue     = (const float*)d_in[8];
    const float* ie     = (const float*)d_in[9];
    const float* lw     = (const float*)d_in[10];
    const float* Wsoc   = (const float*)d_in[11];
    const float* hoW    = (const float*)d_in[12];
    const float* hob    = (const float*)d_in[13];
    const float* hog    = (const float*)d_in[14];
    const float* hobeta = (const float*)d_in[15];
    const float* mpW    = (const float*)d_in[16];
    const float* mpb    = (const float*)d_in[17];
    const float* mpg    = (const float*)d_in[18];
    const float* mpbeta = (const float*)d_in[19];
    float* out = (float*)d_out;

    k_clear_flags<<<(I_N + 255) / 256, 256>>>();
    k_mark<<<B_N / 8, 256>>>(users, pos, ie);
    k_init_u<<<(U_N * DD / 4 + 255) / 256, 256>>>(ue);
    k_init_i<<<(I_N * DD / 4 + 255) / 256, 256>>>(ie);
    k_nw<<<1, 1>>>(lw);

    // LightGCN layer 1 (fused u1 & i1), then layer 2 (u2 full, i2 batch-filtered)
    k_spmm_pass1<<<NNZ_UI / 16, 256>>>(ui_src, ui_dst, ui_w, ue, ie);
    k_spmm_pass2<<<NNZ_UI / 16, 256>>>(ui_src, ui_dst, ui_w);

    // Social layer 1 (full graph)
    k_gemm64<<<592, 256>>>(Wsoc);                          // y = u2 @ Wsoc[0]; n = u2
    k_spmm_soc<<<NNZ_S / 16, 256>>>(s_src, s_dst, s_w, 0); // n = new1
    k_social1<<<592, 256>>>(hoW, hob, hog, hobeta, Wsoc + DD * DD); // s1; y = s1@Wsoc[1]; n = s1

    // Social layer 2 (output needed only at batch users)
    k_spmm_soc<<<NNZ_S / 16, 256>>>(s_src, s_dst, s_w, 1); // n = new2 (batch rows)

    // Epilogue + fusion + scoring, batch rows only
    k_final<<<B_N / 8, 256>>>(users, pos, ue, ie, hoW, hob, hog, hobeta,
                              mpW, mpb, mpg, mpbeta, out);
}

// round 5
// speedup vs baseline: 2.1246x; 1.4397x over previous
#include <cuda_runtime.h>
#include <math.h>

// ---------------- problem constants ----------------
#define U_N 100000
#define I_N 150000
#define DD  64
#define NNZ_UI 2000000
#define NNZ_S  1000000
#define B_N 4096
#define LN_EPS 1e-5f

// ---------------- scratch (device globals) ----------------
__device__ __align__(128) float g_u1[(size_t)U_N * DD];
__device__ __align__(128) float g_u2[(size_t)U_N * DD];
__device__ __align__(128) float g_s1[(size_t)U_N * DD];
__device__ __align__(128) float g_y [(size_t)U_N * DD];   // u2 @ Wsoc0
__device__ __align__(128) float g_y2[(size_t)U_N * DD];   // s1 @ Wsoc1 (needed rows only)
__device__ __align__(128) float g_i1[(size_t)I_N * DD];
__device__ __align__(128) float g_i2[(size_t)I_N * DD];   // batch rows only

// CSR scratch
__device__ int g_cnt_u[U_N], g_cnt_i[I_N], g_cnt_s[U_N];
__device__ int g_off_u[U_N + 1], g_off_i[I_N + 1], g_off_s[U_N + 1];
__device__ int g_cur_u[U_N], g_cur_i[I_N], g_cur_s[U_N];
__device__ int g_part[1024];
__device__ int2 g_pay_us[NNZ_UI];  // keyed by ui_src -> (ui_dst, w)
__device__ int2 g_pay_ui[NNZ_UI];  // keyed by ui_dst -> (ui_src, w)
__device__ int2 g_pay_s [NNZ_S];   // keyed by s_src  -> (s_dst, w)

__device__ int   g_uflag[U_N];     // batch users
__device__ int   g_need [U_N];     // social out-neighbors of batch users
__device__ float g_nw[3];

// ---------------- helpers ----------------
__device__ __forceinline__ float warp_sum(float v) {
    #pragma unroll
    for (int o = 16; o > 0; o >>= 1) v += __shfl_xor_sync(0xffffffffu, v, o);
    return v;
}

// out[2*lane], out[2*lane+1] of (x[0..63] @ W[64x64]); x distributed float2/lane.
__device__ __forceinline__ float2 row_gemm64(float2 xv, const float2* __restrict__ W2, int lane) {
    float2 acc = make_float2(0.f, 0.f);
    #pragma unroll
    for (int kk = 0; kk < 32; kk++) {
        float x0 = __shfl_sync(0xffffffffu, xv.x, kk);
        float x1 = __shfl_sync(0xffffffffu, xv.y, kk);
        float2 w0 = W2[(2 * kk) * 32 + lane];
        float2 w1 = W2[(2 * kk + 1) * 32 + lane];
        acc.x = fmaf(x0, w0.x, fmaf(x1, w1.x, acc.x));
        acc.y = fmaf(x0, w0.y, fmaf(x1, w1.y, acc.y));
    }
    return acc;
}

// pull: acc += sum over CSR row r of w * X[dst]
__device__ __forceinline__ float2 pull_row(const float* __restrict__ X,
        const int* __restrict__ off, const int2* __restrict__ pay,
        int r, int lane, float2 acc) {
    int j = off[r], end = off[r + 1];
    for (; j + 1 < end; j += 2) {
        int2 p0 = __ldg(&pay[j]);
        int2 p1 = __ldg(&pay[j + 1]);
        float w0 = __int_as_float(p0.y), w1 = __int_as_float(p1.y);
        float2 a0 = ((const float2*)(X + (size_t)p0.x * DD))[lane];
        float2 a1 = ((const float2*)(X + (size_t)p1.x * DD))[lane];
        acc.x += w0 * a0.x + w1 * a1.x;
        acc.y += w0 * a0.y + w1 * a1.y;
    }
    if (j < end) {
        int2 p = __ldg(&pay[j]);
        float w0 = __int_as_float(p.y);
        float2 a = ((const float2*)(X + (size_t)p.x * DD))[lane];
        acc.x += w0 * a.x;
        acc.y += w0 * a.y;
    }
    return acc;
}

// generic pull body: out[r] = 0.1*base[r] + sum w*X[nbr]
__device__ __forceinline__ void pull_rows_body(const float* __restrict__ X,
        const float* __restrict__ basesrc,
        const int* __restrict__ off, const int2* __restrict__ pay,
        float* __restrict__ outb, int nrows) {
    int t = blockIdx.x * blockDim.x + threadIdx.x;
    int r = t >> 5, lane = t & 31;
    if (r >= nrows) return;
    float2 b = ((const float2*)(basesrc + (size_t)r * DD))[lane];
    float2 acc = make_float2(0.1f * b.x, 0.1f * b.y);
    acc = pull_row(X, off, pay, r, lane, acc);
    ((float2*)(outb + (size_t)r * DD))[lane] = acc;
}

// ---------------- CSR build ----------------
__global__ void k_zero_misc() {
    int i = blockIdx.x * blockDim.x + threadIdx.x;
    if (i < U_N) { g_cnt_u[i] = 0; g_cnt_s[i] = 0; g_uflag[i] = 0; g_need[i] = 0; }
    if (i < I_N) { g_cnt_i[i] = 0; }
}

__global__ void k_count(const int* __restrict__ key, int E, int* __restrict__ cnt) {
    int e = blockIdx.x * blockDim.x + threadIdx.x;
    if (e < E) atomicAdd(&cnt[key[e]], 1);
}

__global__ void k_blocksum(const int* __restrict__ cnt, int N) {
    __shared__ int sh[256];
    int i = blockIdx.x * 256 + threadIdx.x;
    sh[threadIdx.x] = (i < N) ? cnt[i] : 0;
    __syncthreads();
    for (int o = 128; o > 0; o >>= 1) {
        if (threadIdx.x < o) sh[threadIdx.x] += sh[threadIdx.x + o];
        __syncthreads();
    }
    if (threadIdx.x == 0) g_part[blockIdx.x] = sh[0];
}

__global__ void k_scanpart(int nb) {  // exclusive scan of g_part, single block
    __shared__ int sh[1024];
    int t = threadIdx.x;
    int v = (t < nb) ? g_part[t] : 0;
    sh[t] = v;
    __syncthreads();
    for (int o = 1; o < 1024; o <<= 1) {
        int x = (t >= o) ? sh[t - o] : 0;
        __syncthreads();
        sh[t] += x;
        __syncthreads();
    }
    if (t < nb) g_part[t] = sh[t] - v;
}

__global__ void k_offsets(const int* __restrict__ cnt, int N, int E,
                          int* __restrict__ off, int* __restrict__ cur) {
    __shared__ int sh[256];
    int b = blockIdx.x, t = threadIdx.x, i = b * 256 + t;
    int v = (i < N) ? cnt[i] : 0;
    sh[t] = v;
    __syncthreads();
    for (int o = 1; o < 256; o <<= 1) {
        int x = (t >= o) ? sh[t - o] : 0;
        __syncthreads();
        sh[t] += x;
        __syncthreads();
    }
    if (i < N) {
        int e = g_part[b] + sh[t] - v;
        off[i] = e;
        cur[i] = e;
    }
    if (i == 0) off[N] = E;
}

__global__ void k_permute(const int* __restrict__ key, const int* __restrict__ other,
                          const float* __restrict__ w, int E,
                          int* __restrict__ cur, int2* __restrict__ pay) {
    int e = blockIdx.x * blockDim.x + threadIdx.x;
    if (e >= E) return;
    int k = key[e];
    int pos = atomicAdd(&cur[k], 1);
    pay[pos] = make_int2(other[e], __float_as_int(w[e]));
}

// ---------------- marking + small ----------------
__global__ void k_markbatch(const int* __restrict__ users) {
    int i = blockIdx.x * blockDim.x + threadIdx.x;
    if (i < B_N) g_uflag[users[i]] = 1;
}
__global__ void k_mark2(const int* __restrict__ ssrc, const int* __restrict__ sdst) {
    int e = blockIdx.x * blockDim.x + threadIdx.x;
    if (e >= NNZ_S) return;
    if (g_uflag[ssrc[e]]) g_need[sdst[e]] = 1;
}
__global__ void k_nw(const float* __restrict__ lw) {
    float a = lw[0], b = lw[1], c = lw[2];
    float m = fmaxf(a, fmaxf(b, c));
    float e0 = expf(a - m), e1 = expf(b - m), e2 = expf(c - m);
    float inv = 1.f / (e0 + e1 + e2);
    g_nw[0] = e0 * inv; g_nw[1] = e1 * inv; g_nw[2] = e2 * inv;
}

// ---------------- pull kernels ----------------
__global__ void k_pull_u1(const float* __restrict__ ue, const float* __restrict__ ie) {
    pull_rows_body(ie, ue, g_off_u, g_pay_us, g_u1, U_N);
}
__global__ void k_pull_i1(const float* __restrict__ ue, const float* __restrict__ ie) {
    pull_rows_body(ue, ie, g_off_i, g_pay_ui, g_i1, I_N);
}
__global__ void k_pull_u2(const float* __restrict__ ue) {
    pull_rows_body(g_i1, ue, g_off_u, g_pay_us, g_u2, U_N);
}
__global__ void k_pull_i2(const int* __restrict__ pos, const float* __restrict__ ie) {
    int t = blockIdx.x * blockDim.x + threadIdx.x;
    int wb = t >> 5, lane = t & 31;
    if (wb >= B_N) return;
    int p = pos[wb];
    float2 b = ((const float2*)(ie + (size_t)p * DD))[lane];
    float2 acc = make_float2(0.1f * b.x, 0.1f * b.y);
    acc = pull_row(g_u1, g_off_i, g_pay_ui, p, lane, acc);
    ((float2*)(g_i2 + (size_t)p * DD))[lane] = acc;
}

// ---------------- dense ----------------
// y = u2 @ Wsoc0 (all rows)
__global__ void k_gemm_y(const float* __restrict__ Wg) {
    __shared__ float sW[64 * 64];
    for (int i = threadIdx.x; i < 1024; i += blockDim.x)
        ((float4*)sW)[i] = ((const float4*)Wg)[i];
    __syncthreads();
    int lane = threadIdx.x & 31;
    int gw = (blockIdx.x * blockDim.x + threadIdx.x) >> 5;
    int tw = (gridDim.x * blockDim.x) >> 5;
    for (int r = gw; r < U_N; r += tw) {
        float2 xv = ((const float2*)(g_u2 + (size_t)r * DD))[lane];
        float2 acc = row_gemm64(xv, (const float2*)sW, lane);
        ((float2*)(g_y + (size_t)r * DD))[lane] = acc;
    }
}

// social layer-1 (needed rows only): pull + gated epilogue + layer-2 input gemm
__global__ void k_soc1(const float* __restrict__ hoW, const float* __restrict__ hob,
                       const float* __restrict__ hog, const float* __restrict__ hobeta,
                       const float* __restrict__ Wsoc1) {
    __shared__ float sW[64 * 64];
    __shared__ float sV[64 * 64];
    for (int i = threadIdx.x; i < 1024; i += blockDim.x) {
        ((float4*)sW)[i] = ((const float4*)hoW)[i];
        ((float4*)sV)[i] = ((const float4*)Wsoc1)[i];
    }
    __syncthreads();
    int lane = threadIdx.x & 31;
    int j0 = 2 * lane, j1 = 2 * lane + 1;
    int gw = (blockIdx.x * blockDim.x + threadIdx.x) >> 5;
    int tw = (gridDim.x * blockDim.x) >> 5;
    float b0 = hob[j0], b1 = hob[j1];
    float gg0 = hog[j0], gg1 = hog[j1];
    float be0 = hobeta[j0], be1 = hobeta[j1];
    for (int r = gw; r < U_N; r += tw) {
        if (!(g_uflag[r] | g_need[r])) continue;
        float2 cv = ((const float2*)(g_u2 + (size_t)r * DD))[lane];
        float2 nv = pull_row(g_y, g_off_s, g_pay_s, r, lane, cv);  // new = cur + neighbor
        float2 hv = row_gemm64(nv, (const float2*)sW, lane);
        hv.x += b0; hv.y += b1;
        float mu  = warp_sum(hv.x + hv.y) * (1.f / 64.f);
        float msq = warp_sum(hv.x * hv.x + hv.y * hv.y) * (1.f / 64.f);
        float inv = rsqrtf(msq - mu * mu + LN_EPS);
        float t0 = (hv.x - mu) * inv * gg0 + be0;
        float t1 = (hv.y - mu) * inv * gg1 + be1;
        t0 = t0 >= 0.f ? t0 : 0.01f * t0;
        t1 = t1 >= 0.f ? t1 : 0.01f * t1;
        float ga = 1.f / (1.f + expf(-t0));
        float gb = 1.f / (1.f + expf(-t1));
        float2 o;
        o.x = ga * nv.x + (1.f - ga) * cv.x;
        o.y = gb * nv.y + (1.f - gb) * cv.y;
        ((float2*)(g_s1 + (size_t)r * DD))[lane] = o;
        float2 y2 = row_gemm64(o, (const float2*)sV, lane);
        ((float2*)(g_y2 + (size_t)r * DD))[lane] = y2;
    }
}

// final: soc layer-2 pull + epilogue + aggregates + metapath fusion + score
__global__ void k_final(const int* __restrict__ users, const int* __restrict__ pos,
                        const float* __restrict__ ue, const float* __restrict__ ie,
                        const float* __restrict__ hoW, const float* __restrict__ hob,
                        const float* __restrict__ hog, const float* __restrict__ hobeta,
                        const float* __restrict__ mpW, const float* __restrict__ mpb,
                        const float* __restrict__ mpg, const float* __restrict__ mpbeta,
                        float* __restrict__ out) {
    __shared__ float sM[128 * 64];  // mpW staged (32KB)
    for (int i = threadIdx.x; i < 2048; i += blockDim.x)
        ((float4*)sM)[i] = ((const float4*)mpW)[i];
    __syncthreads();
    int t = blockIdx.x * blockDim.x + threadIdx.x;
    int wb = t >> 5, lane = t & 31;
    if (wb >= B_N) return;
    int u = users[wb], p = pos[wb];
    int j0 = 2 * lane, j1 = 2 * lane + 1;
    float nw0 = g_nw[0], nw1 = g_nw[1], nw2 = g_nw[2];

    // ---- social layer 2: pull new2 = s1[u] + sum w*y2[dst], then gated epilogue
    float2 cv = ((const float2*)(g_s1 + (size_t)u * DD))[lane];
    float2 nv = pull_row(g_y2, g_off_s, g_pay_s, u, lane, cv);
    float2 hv = row_gemm64(nv, (const float2*)hoW, lane);  // hoW via L2 (tiny kernel)
    hv.x += hob[j0]; hv.y += hob[j1];
    float mu  = warp_sum(hv.x + hv.y) * (1.f / 64.f);
    float msq = warp_sum(hv.x * hv.x + hv.y * hv.y) * (1.f / 64.f);
    float inv = rsqrtf(msq - mu * mu + LN_EPS);
    float t0 = (hv.x - mu) * inv * hog[j0] + hobeta[j0];
    float t1 = (hv.y - mu) * inv * hog[j1] + hobeta[j1];
    t0 = t0 >= 0.f ? t0 : 0.01f * t0;
    t1 = t1 >= 0.f ? t1 : 0.01f * t1;
    float ga = 1.f / (1.f + expf(-t0));
    float gb = 1.f / (1.f + expf(-t1));
    float2 s2;
    s2.x = ga * nv.x + (1.f - ga) * cv.x;
    s2.y = gb * nv.y + (1.f - gb) * cv.y;

    // ---- aggregates
    float2 u2v = ((const float2*)(g_u2 + (size_t)u * DD))[lane];
    float2 swv;  // s_list = [u2, s1, s2]
    swv.x = nw0 * u2v.x + nw1 * cv.x + nw2 * s2.x;
    swv.y = nw0 * u2v.y + nw1 * cv.y + nw2 * s2.y;
    float2 e0 = ((const float2*)(ue + (size_t)u * DD))[lane];
    float2 u1v = ((const float2*)(g_u1 + (size_t)u * DD))[lane];
    float2 uwv;  // u_list = [E0, u1, u2]
    uwv.x = nw0 * e0.x + nw1 * u1v.x + nw2 * u2v.x;
    uwv.y = nw0 * e0.y + nw1 * u1v.y + nw2 * u2v.y;

    // ---- metapath fusion
    float2 acc  = row_gemm64(uwv, (const float2*)sM, lane);
    float2 acc2 = row_gemm64(swv, (const float2*)sM + 64 * 32, lane);
    acc.x += acc2.x + mpb[j0];
    acc.y += acc2.y + mpb[j1];
    float mu2  = warp_sum(acc.x + acc.y) * (1.f / 64.f);
    float msq2 = warp_sum(acc.x * acc.x + acc.y * acc.y) * (1.f / 64.f);
    float inv2 = rsqrtf(msq2 - mu2 * mu2 + LN_EPS);
    float f0 = (acc.x - mu2) * inv2 * mpg[j0] + mpbeta[j0];
    float f1 = (acc.y - mu2) * inv2 * mpg[j1] + mpbeta[j1];
    f0 = f0 >= 0.f ? f0 : 0.01f * f0;
    f1 = f1 >= 0.f ? f1 : 0.01f * f1;

    // ---- item side + dot
    float2 ei  = ((const float2*)(ie + (size_t)p * DD))[lane];
    float2 i1v = ((const float2*)(g_i1 + (size_t)p * DD))[lane];
    float2 i2v = ((const float2*)(g_i2 + (size_t)p * DD))[lane];
    float iw0 = nw0 * ei.x + nw1 * i1v.x + nw2 * i2v.x;
    float iw1 = nw0 * ei.y + nw1 * i1v.y + nw2 * i2v.y;
    float sc = warp_sum(f0 * iw0 + f1 * iw1);
    if (lane == 0) out[wb] = sc;
}

// ---------------- launch ----------------
extern "C" void kernel_launch(void* const* d_in, const int* in_sizes, int n_in,
                              void* d_out, int out_size) {
    (void)in_sizes; (void)n_in; (void)out_size;
    const int*   users  = (const int*)d_in[0];
    const int*   pos    = (const int*)d_in[1];
    const int*   ui_src = (const int*)d_in[2];
    const int*   ui_dst = (const int*)d_in[3];
    const float* ui_w   = (const float*)d_in[4];
    const int*   s_src  = (const int*)d_in[5];
    const int*   s_dst  = (const int*)d_in[6];
    const float* s_w    = (const float*)d_in[7];
    const float* ue     = (const float*)d_in[8];
    const float* ie     = (const float*)d_in[9];
    const float* lw     = (const float*)d_in[10];
    const float* Wsoc   = (const float*)d_in[11];
    const float* hoW    = (const float*)d_in[12];
    const float* hob    = (const float*)d_in[13];
    const float* hog    = (const float*)d_in[14];
    const float* hobeta = (const float*)d_in[15];
    const float* mpW    = (const float*)d_in[16];
    const float* mpb    = (const float*)d_in[17];
    const float* mpg    = (const float*)d_in[18];
    const float* mpbeta = (const float*)d_in[19];
    float* out = (float*)d_out;

    const int NB_U = (U_N + 255) / 256;   // 391
    const int NB_I = (I_N + 255) / 256;   // 586

    // --- CSR builds
    k_zero_misc<<<NB_I, 256>>>();
    {
        int* cu; cudaGetSymbolAddress((void**)&cu, g_cnt_u);
        int* ci; cudaGetSymbolAddress((void**)&ci, g_cnt_i);
        int* cs; cudaGetSymbolAddress((void**)&cs, g_cnt_s);
        int* ou; cudaGetSymbolAddress((void**)&ou, g_off_u);
        int* oi; cudaGetSymbolAddress((void**)&oi, g_off_i);
        int* os; cudaGetSymbolAddress((void**)&os, g_off_s);
        int* ru; cudaGetSymbolAddress((void**)&ru, g_cur_u);
        int* ri; cudaGetSymbolAddress((void**)&ri, g_cur_i);
        int* rs; cudaGetSymbolAddress((void**)&rs, g_cur_s);
        int2* pus; cudaGetSymbolAddress((void**)&pus, g_pay_us);
        int2* pui; cudaGetSymbolAddress((void**)&pui, g_pay_ui);
        int2* ps;  cudaGetSymbolAddress((void**)&ps,  g_pay_s);

        k_count<<<(NNZ_UI + 255) / 256, 256>>>(ui_src, NNZ_UI, cu);
        k_blocksum<<<NB_U, 256>>>(cu, U_N);
        k_scanpart<<<1, 1024>>>(NB_U);
        k_offsets<<<NB_U, 256>>>(cu, U_N, NNZ_UI, ou, ru);
        k_permute<<<(NNZ_UI + 255) / 256, 256>>>(ui_src, ui_dst, ui_w, NNZ_UI, ru, pus);

        k_count<<<(NNZ_UI + 255) / 256, 256>>>(ui_dst, NNZ_UI, ci);
        k_blocksum<<<NB_I, 256>>>(ci, I_N);
        k_scanpart<<<1, 1024>>>(NB_I);
        k_offsets<<<NB_I, 256>>>(ci, I_N, NNZ_UI, oi, ri);
        k_permute<<<(NNZ_UI + 255) / 256, 256>>>(ui_dst, ui_src, ui_w, NNZ_UI, ri, pui);

        k_count<<<(NNZ_S + 255) / 256, 256>>>(s_src, NNZ_S, cs);
        k_blocksum<<<NB_U, 256>>>(cs, U_N);
        k_scanpart<<<1, 1024>>>(NB_U);
        k_offsets<<<NB_U, 256>>>(cs, U_N, NNZ_S, os, rs);
        k_permute<<<(NNZ_S + 255) / 256, 256>>>(s_src, s_dst, s_w, NNZ_S, rs, ps);
    }

    // --- marking + softmax
    k_markbatch<<<(B_N + 255) / 256, 256>>>(users);
    k_mark2<<<(NNZ_S + 255) / 256, 256>>>(s_src, s_dst);
    k_nw<<<1, 1>>>(lw);

    // --- LightGCN pulls
    k_pull_u1<<<(U_N * 32 + 255) / 256, 256>>>(ue, ie);
    k_pull_i1<<<(I_N * 32 + 255) / 256, 256>>>(ue, ie);
    k_pull_u2<<<(U_N * 32 + 255) / 256, 256>>>(ue);
    k_pull_i2<<<(B_N * 32 + 255) / 256, 256>>>(pos, ie);

    // --- social
    k_gemm_y<<<1184, 256>>>(Wsoc);                                 // y = u2 @ Wsoc0
    k_soc1<<<1184, 256>>>(hoW, hob, hog, hobeta, Wsoc + DD * DD);  // s1, y2 (needed rows)

    // --- final
    k_final<<<(B_N * 32 + 255) / 256, 256>>>(users, pos, ue, ie, hoW, hob, hog, hobeta,
                                             mpW, mpb, mpg, mpbeta, out);
}

// round 6
// speedup vs baseline: 2.2859x; 1.0759x over previous
#include <cuda_runtime.h>
#include <math.h>

// ---------------- problem constants ----------------
#define U_N 100000
#define I_N 150000
#define DD  64
#define NNZ_UI 2000000
#define NNZ_S  1000000
#define B_N 4096
#define LN_EPS 1e-5f

// ---------------- scratch (device globals) ----------------
__device__ __align__(128) float g_u1[(size_t)U_N * DD];
__device__ __align__(128) float g_u2[(size_t)U_N * DD];
__device__ __align__(128) float g_s1[(size_t)U_N * DD];
__device__ __align__(128) float g_y [(size_t)U_N * DD];   // u2 @ Wsoc0
__device__ __align__(128) float g_y2[(size_t)U_N * DD];   // s1 @ Wsoc1 (needed rows only)
__device__ __align__(128) float g_i1[(size_t)I_N * DD];
__device__ __align__(128) float g_i2[(size_t)I_N * DD];   // batch rows only

// CSR scratch (segment-assigned, unordered)
__device__ int g_cnt_u[U_N], g_cnt_i[I_N], g_cnt_s[U_N];
__device__ int g_off_u[U_N], g_off_i[I_N], g_off_s[U_N];
__device__ int g_cur_u[U_N], g_cur_i[I_N], g_cur_s[U_N];
__device__ int g_tot[4];
__device__ int2 g_pay_us[NNZ_UI];  // keyed by ui_src -> (ui_dst, w)
__device__ int2 g_pay_ui[NNZ_UI];  // keyed by ui_dst -> (ui_src, w)
__device__ int2 g_pay_s [NNZ_S];   // keyed by s_src  -> (s_dst, w)

__device__ int   g_uflag[U_N];     // batch users
__device__ int   g_need [U_N];     // social out-neighbors of batch users
__device__ float g_nw[3];

// ---------------- helpers ----------------
__device__ __forceinline__ float warp_sum(float v) {
    #pragma unroll
    for (int o = 16; o > 0; o >>= 1) v += __shfl_xor_sync(0xffffffffu, v, o);
    return v;
}

// out[2*lane], out[2*lane+1] of (x[0..63] @ W[64x64]); x distributed float2/lane.
__device__ __forceinline__ float2 row_gemm64(float2 xv, const float2* __restrict__ W2, int lane) {
    float2 acc = make_float2(0.f, 0.f);
    #pragma unroll
    for (int kk = 0; kk < 32; kk++) {
        float x0 = __shfl_sync(0xffffffffu, xv.x, kk);
        float x1 = __shfl_sync(0xffffffffu, xv.y, kk);
        float2 w0 = W2[(2 * kk) * 32 + lane];
        float2 w1 = W2[(2 * kk + 1) * 32 + lane];
        acc.x = fmaf(x0, w0.x, fmaf(x1, w1.x, acc.x));
        acc.y = fmaf(x0, w0.y, fmaf(x1, w1.y, acc.y));
    }
    return acc;
}

// pull: acc += sum over CSR segment [off, off+cnt) of w * X[nbr]
__device__ __forceinline__ float2 pull_row(const float* __restrict__ X,
        const int* __restrict__ off, const int* __restrict__ cnt,
        const int2* __restrict__ pay, int r, int lane, float2 acc) {
    int j = off[r], end = j + cnt[r];
    for (; j + 1 < end; j += 2) {
        int2 p0 = __ldg(&pay[j]);
        int2 p1 = __ldg(&pay[j + 1]);
        float w0 = __int_as_float(p0.y), w1 = __int_as_float(p1.y);
        float2 a0 = ((const float2*)(X + (size_t)p0.x * DD))[lane];
        float2 a1 = ((const float2*)(X + (size_t)p1.x * DD))[lane];
        acc.x += w0 * a0.x + w1 * a1.x;
        acc.y += w0 * a0.y + w1 * a1.y;
    }
    if (j < end) {
        int2 p = __ldg(&pay[j]);
        float w0 = __int_as_float(p.y);
        float2 a = ((const float2*)(X + (size_t)p.x * DD))[lane];
        acc.x += w0 * a.x;
        acc.y += w0 * a.y;
    }
    return acc;
}

// ---------------- build kernels ----------------
__global__ void k_zero_misc() {
    int i = blockIdx.x * blockDim.x + threadIdx.x;
    if (i < U_N) { g_cnt_u[i] = 0; g_cnt_s[i] = 0; g_uflag[i] = 0; g_need[i] = 0; }
    if (i < I_N) { g_cnt_i[i] = 0; }
    if (i < 4)   { g_tot[i] = 0; }
}

// mark batch users + compute softmax weights
__global__ void k_mark(const int* __restrict__ users, const float* __restrict__ lw) {
    int i = blockIdx.x * blockDim.x + threadIdx.x;
    if (i < B_N) g_uflag[users[i]] = 1;
    if (i == 0) {
        float a = lw[0], b = lw[1], c = lw[2];
        float m = fmaxf(a, fmaxf(b, c));
        float e0 = expf(a - m), e1 = expf(b - m), e2 = expf(c - m);
        float inv = 1.f / (e0 + e1 + e2);
        g_nw[0] = e0 * inv; g_nw[1] = e1 * inv; g_nw[2] = e2 * inv;
    }
}

// one pass over both edge lists: all three degree counts + needed-set marking
__global__ void k_count_all(const int* __restrict__ ui_src, const int* __restrict__ ui_dst,
                            const int* __restrict__ s_src, const int* __restrict__ s_dst) {
    int e = blockIdx.x * blockDim.x + threadIdx.x;
    if (e < NNZ_UI) {
        atomicAdd(&g_cnt_u[ui_src[e]], 1);
        atomicAdd(&g_cnt_i[ui_dst[e]], 1);
    }
    if (e < NNZ_S) {
        int s = s_src[e];
        atomicAdd(&g_cnt_s[s], 1);
        if (g_uflag[s]) g_need[s_dst[e]] = 1;
    }
}

// segment assignment via atomic bump (CSR rows in arbitrary order — pulls don't care)
__global__ void k_assign() {
    int i = blockIdx.x * blockDim.x + threadIdx.x;
    if (i < U_N) {
        int c = g_cnt_u[i];
        int o = atomicAdd(&g_tot[0], c);
        g_off_u[i] = o; g_cur_u[i] = o;
        c = g_cnt_s[i];
        o = atomicAdd(&g_tot[2], c);
        g_off_s[i] = o; g_cur_s[i] = o;
    }
    if (i < I_N) {
        int c = g_cnt_i[i];
        int o = atomicAdd(&g_tot[1], c);
        g_off_i[i] = o; g_cur_i[i] = o;
    }
}

__global__ void k_permute_all(const int* __restrict__ ui_src, const int* __restrict__ ui_dst,
                              const float* __restrict__ ui_w,
                              const int* __restrict__ s_src, const int* __restrict__ s_dst,
                              const float* __restrict__ s_w) {
    int e = blockIdx.x * blockDim.x + threadIdx.x;
    if (e < NNZ_UI) {
        int s = ui_src[e], d = ui_dst[e];
        int wbits = __float_as_int(ui_w[e]);
        g_pay_us[atomicAdd(&g_cur_u[s], 1)] = make_int2(d, wbits);
        g_pay_ui[atomicAdd(&g_cur_i[d], 1)] = make_int2(s, wbits);
    }
    if (e < NNZ_S) {
        int s = s_src[e];
        g_pay_s[atomicAdd(&g_cur_s[s], 1)] = make_int2(s_dst[e], __float_as_int(s_w[e]));
    }
}

// ---------------- pull phase 1: u1 (users) + i1 (items), one launch ----------------
__global__ void k_pull1(const float* __restrict__ ue, const float* __restrict__ ie) {
    int t = blockIdx.x * blockDim.x + threadIdx.x;
    int r = t >> 5, lane = t & 31;
    if (r < U_N) {
        float2 b = ((const float2*)(ue + (size_t)r * DD))[lane];
        float2 acc = make_float2(0.1f * b.x, 0.1f * b.y);
        acc = pull_row(ie, g_off_u, g_cnt_u, g_pay_us, r, lane, acc);
        ((float2*)(g_u1 + (size_t)r * DD))[lane] = acc;
    } else {
        int rr = r - U_N;
        if (rr >= I_N) return;
        float2 b = ((const float2*)(ie + (size_t)rr * DD))[lane];
        float2 acc = make_float2(0.1f * b.x, 0.1f * b.y);
        acc = pull_row(ue, g_off_i, g_cnt_i, g_pay_ui, rr, lane, acc);
        ((float2*)(g_i1 + (size_t)rr * DD))[lane] = acc;
    }
}

// ---------------- pull phase 2: u2 + y = u2@Wsoc0 (users) and i2 (batch items) ----------------
__global__ void k_pull2(const float* __restrict__ ue, const float* __restrict__ ie,
                        const int* __restrict__ pos, const float* __restrict__ Wsoc0) {
    __shared__ float sW[64 * 64];
    for (int i = threadIdx.x; i < 1024; i += blockDim.x)
        ((float4*)sW)[i] = ((const float4*)Wsoc0)[i];
    __syncthreads();
    int t = blockIdx.x * blockDim.x + threadIdx.x;
    int r = t >> 5, lane = t & 31;
    if (r < U_N) {
        float2 b = ((const float2*)(ue + (size_t)r * DD))[lane];
        float2 acc = make_float2(0.1f * b.x, 0.1f * b.y);
        acc = pull_row(g_i1, g_off_u, g_cnt_u, g_pay_us, r, lane, acc);
        ((float2*)(g_u2 + (size_t)r * DD))[lane] = acc;
        float2 yv = row_gemm64(acc, (const float2*)sW, lane);
        ((float2*)(g_y + (size_t)r * DD))[lane] = yv;
    } else {
        int wb = r - U_N;
        if (wb >= B_N) return;
        int p = pos[wb];
        float2 b = ((const float2*)(ie + (size_t)p * DD))[lane];
        float2 acc = make_float2(0.1f * b.x, 0.1f * b.y);
        acc = pull_row(g_u1, g_off_i, g_cnt_i, g_pay_ui, p, lane, acc);
        ((float2*)(g_i2 + (size_t)p * DD))[lane] = acc;
    }
}

// ---------------- social layer-1 (needed rows): pull + gated epilogue + layer-2 input gemm
__global__ void k_soc1(const float* __restrict__ hoW, const float* __restrict__ hob,
                       const float* __restrict__ hog, const float* __restrict__ hobeta,
                       const float* __restrict__ Wsoc1) {
    __shared__ float sW[64 * 64];
    __shared__ float sV[64 * 64];
    for (int i = threadIdx.x; i < 1024; i += blockDim.x) {
        ((float4*)sW)[i] = ((const float4*)hoW)[i];
        ((float4*)sV)[i] = ((const float4*)Wsoc1)[i];
    }
    __syncthreads();
    int lane = threadIdx.x & 31;
    int j0 = 2 * lane, j1 = 2 * lane + 1;
    int gw = (blockIdx.x * blockDim.x + threadIdx.x) >> 5;
    int tw = (gridDim.x * blockDim.x) >> 5;
    float b0 = hob[j0], b1 = hob[j1];
    float gg0 = hog[j0], gg1 = hog[j1];
    float be0 = hobeta[j0], be1 = hobeta[j1];
    for (int r = gw; r < U_N; r += tw) {
        if (!(g_uflag[r] | g_need[r])) continue;
        float2 cv = ((const float2*)(g_u2 + (size_t)r * DD))[lane];
        float2 nv = pull_row(g_y, g_off_s, g_cnt_s, g_pay_s, r, lane, cv);  // new = cur + nbr
        float2 hv = row_gemm64(nv, (const float2*)sW, lane);
        hv.x += b0; hv.y += b1;
        float mu  = warp_sum(hv.x + hv.y) * (1.f / 64.f);
        float msq = warp_sum(hv.x * hv.x + hv.y * hv.y) * (1.f / 64.f);
        float inv = rsqrtf(msq - mu * mu + LN_EPS);
        float t0 = (hv.x - mu) * inv * gg0 + be0;
        float t1 = (hv.y - mu) * inv * gg1 + be1;
        t0 = t0 >= 0.f ? t0 : 0.01f * t0;
        t1 = t1 >= 0.f ? t1 : 0.01f * t1;
        float ga = 1.f / (1.f + expf(-t0));
        float gb = 1.f / (1.f + expf(-t1));
        float2 o;
        o.x = ga * nv.x + (1.f - ga) * cv.x;
        o.y = gb * nv.y + (1.f - gb) * cv.y;
        ((float2*)(g_s1 + (size_t)r * DD))[lane] = o;
        float2 y2 = row_gemm64(o, (const float2*)sV, lane);
        ((float2*)(g_y2 + (size_t)r * DD))[lane] = y2;
    }
}

// ---------------- final: soc layer-2 pull + epilogue + aggregates + fusion + score
__global__ void k_final(const int* __restrict__ users, const int* __restrict__ pos,
                        const float* __restrict__ ue, const float* __restrict__ ie,
                        const float* __restrict__ hoW, const float* __restrict__ hob,
                        const float* __restrict__ hog, const float* __restrict__ hobeta,
                        const float* __restrict__ mpW, const float* __restrict__ mpb,
                        const float* __restrict__ mpg, const float* __restrict__ mpbeta,
                        float* __restrict__ out) {
    __shared__ float sM[128 * 64];  // mpW staged (32KB)
    for (int i = threadIdx.x; i < 2048; i += blockDim.x)
        ((float4*)sM)[i] = ((const float4*)mpW)[i];
    __syncthreads();
    int t = blockIdx.x * blockDim.x + threadIdx.x;
    int wb = t >> 5, lane = t & 31;
    if (wb >= B_N) return;
    int u = users[wb], p = pos[wb];
    int j0 = 2 * lane, j1 = 2 * lane + 1;
    float nw0 = g_nw[0], nw1 = g_nw[1], nw2 = g_nw[2];

    // ---- social layer 2: new2 = s1[u] + sum w*y2[dst], then gated epilogue
    float2 cv = ((const float2*)(g_s1 + (size_t)u * DD))[lane];
    float2 nv = pull_row(g_y2, g_off_s, g_cnt_s, g_pay_s, u, lane, cv);
    float2 hv = row_gemm64(nv, (const float2*)hoW, lane);
    hv.x += hob[j0]; hv.y += hob[j1];
    float mu  = warp_sum(hv.x + hv.y) * (1.f / 64.f);
    float msq = warp_sum(hv.x * hv.x + hv.y * hv.y) * (1.f / 64.f);
    float inv = rsqrtf(msq - mu * mu + LN_EPS);
    float t0 = (hv.x - mu) * inv * hog[j0] + hobeta[j0];
    float t1 = (hv.y - mu) * inv * hog[j1] + hobeta[j1];
    t0 = t0 >= 0.f ? t0 : 0.01f * t0;
    t1 = t1 >= 0.f ? t1 : 0.01f * t1;
    float ga = 1.f / (1.f + expf(-t0));
    float gb = 1.f / (1.f + expf(-t1));
    float2 s2;
    s2.x = ga * nv.x + (1.f - ga) * cv.x;
    s2.y = gb * nv.y + (1.f - gb) * cv.y;

    // ---- aggregates
    float2 u2v = ((const float2*)(g_u2 + (size_t)u * DD))[lane];
    float2 swv;  // s_list = [u2, s1, s2]
    swv.x = nw0 * u2v.x + nw1 * cv.x + nw2 * s2.x;
    swv.y = nw0 * u2v.y + nw1 * cv.y + nw2 * s2.y;
    float2 e0 = ((const float2*)(ue + (size_t)u * DD))[lane];
    float2 u1v = ((const float2*)(g_u1 + (size_t)u * DD))[lane];
    float2 uwv;  // u_list = [E0, u1, u2]
    uwv.x = nw0 * e0.x + nw1 * u1v.x + nw2 * u2v.x;
    uwv.y = nw0 * e0.y + nw1 * u1v.y + nw2 * u2v.y;

    // ---- metapath fusion
    float2 acc  = row_gemm64(uwv, (const float2*)sM, lane);
    float2 acc2 = row_gemm64(swv, (const float2*)sM + 64 * 32, lane);
    acc.x += acc2.x + mpb[j0];
    acc.y += acc2.y + mpb[j1];
    float mu2  = warp_sum(acc.x + acc.y) * (1.f / 64.f);
    float msq2 = warp_sum(acc.x * acc.x + acc.y * acc.y) * (1.f / 64.f);
    float inv2 = rsqrtf(msq2 - mu2 * mu2 + LN_EPS);
    float f0 = (acc.x - mu2) * inv2 * mpg[j0] + mpbeta[j0];
    float f1 = (acc.y - mu2) * inv2 * mpg[j1] + mpbeta[j1];
    f0 = f0 >= 0.f ? f0 : 0.01f * f0;
    f1 = f1 >= 0.f ? f1 : 0.01f * f1;

    // ---- item side + dot
    float2 ei  = ((const float2*)(ie + (size_t)p * DD))[lane];
    float2 i1v = ((const float2*)(g_i1 + (size_t)p * DD))[lane];
    float2 i2v = ((const float2*)(g_i2 + (size_t)p * DD))[lane];
    float iw0 = nw0 * ei.x + nw1 * i1v.x + nw2 * i2v.x;
    float iw1 = nw0 * ei.y + nw1 * i1v.y + nw2 * i2v.y;
    float sc = warp_sum(f0 * iw0 + f1 * iw1);
    if (lane == 0) out[wb] = sc;
}

// ---------------- launch ----------------
extern "C" void kernel_launch(void* const* d_in, const int* in_sizes, int n_in,
                              void* d_out, int out_size) {
    (void)in_sizes; (void)n_in; (void)out_size;
    const int*   users  = (const int*)d_in[0];
    const int*   pos    = (const int*)d_in[1];
    const int*   ui_src = (const int*)d_in[2];
    const int*   ui_dst = (const int*)d_in[3];
    const float* ui_w   = (const float*)d_in[4];
    const int*   s_src  = (const int*)d_in[5];
    const int*   s_dst  = (const int*)d_in[6];
    const float* s_w    = (const float*)d_in[7];
    const float* ue     = (const float*)d_in[8];
    const float* ie     = (const float*)d_in[9];
    const float* lw     = (const float*)d_in[10];
    const float* Wsoc   = (const float*)d_in[11];
    const float* hoW    = (const float*)d_in[12];
    const float* hob    = (const float*)d_in[13];
    const float* hog    = (const float*)d_in[14];
    const float* hobeta = (const float*)d_in[15];
    const float* mpW    = (const float*)d_in[16];
    const float* mpb    = (const float*)d_in[17];
    const float* mpg    = (const float*)d_in[18];
    const float* mpbeta = (const float*)d_in[19];
    float* out = (float*)d_out;

    // --- build (5 launches)
    k_zero_misc<<<(I_N + 255) / 256, 256>>>();
    k_mark<<<(B_N + 255) / 256, 256>>>(users, lw);
    k_count_all<<<(NNZ_UI + 255) / 256, 256>>>(ui_src, ui_dst, s_src, s_dst);
    k_assign<<<(I_N + 255) / 256, 256>>>();
    k_permute_all<<<(NNZ_UI + 255) / 256, 256>>>(ui_src, ui_dst, ui_w, s_src, s_dst, s_w);

    // --- pulls (2 launches)
    k_pull1<<<((U_N + I_N) * 32 + 255) / 256, 256>>>(ue, ie);
    k_pull2<<<((U_N + B_N) * 32 + 255) / 256, 256>>>(ue, ie, pos, Wsoc);

    // --- social + final (2 launches)
    k_soc1<<<1184, 256>>>(hoW, hob, hog, hobeta, Wsoc + DD * DD);
    k_final<<<(B_N * 32 + 255) / 256, 256>>>(users, pos, ue, ie, hoW, hob, hog, hobeta,
                                             mpW, mpb, mpg, mpbeta, out);
}